// round 16
// baseline (speedup 1.0000x reference)
#include <cuda_runtime.h>
#include <cuda_fp16.h>
#include <math.h>
#include <stdint.h>

#define TT 128
#define DMM 32

typedef uint32_t u32;

// ---- f32 region (float offsets) ----
#define F_BO   0
#define F_B2   32
#define F_G1   64
#define F_BE1  96
#define F_G2   128
#define F_BE2  160
#define F_B1   192          // 128 floats
#define F_OS   320          // [128][36] f32 (Wo out, then FFN out)
#define F_END  (320 + 128*36)
// ---- half region (half offsets), starts at byte 4*F_END ----
#define H_XN   0            // [128][40]  xn -> at -> zn
#define H_QS   5120         // [128][40]  Q  -> W1t[128][40]
#define H_KS   10240        // [128][40]  K  -> W2t[32][136]
#define H_VT   15360        // [32][136]  V^T (dv-major, keys contiguous)
#define H_WB   19712        // [96][40] WqkvT -> WoT[32][40]
#define H_END  23552
#define SMEM_BYTES (4*F_END + 2*H_END)   // 66816

__device__ __forceinline__ u32 sadd(const __half* p) {
    return static_cast<u32>(__cvta_generic_to_shared(p));
}
__device__ __forceinline__ void ldsm4(u32 (&r)[4], u32 a) {
    asm volatile("ldmatrix.sync.aligned.m8n8.x4.shared.b16 {%0,%1,%2,%3}, [%4];"
                 : "=r"(r[0]), "=r"(r[1]), "=r"(r[2]), "=r"(r[3]) : "r"(a));
}
// D += A(16x16,row) * B(16x8,col), f16 in, f32 accum
__device__ __forceinline__ void mma16a(float (&d)[4], const u32 (&a)[4], u32 b0, u32 b1) {
    asm("mma.sync.aligned.m16n8k16.row.col.f32.f16.f16.f32 "
        "{%0,%1,%2,%3}, {%4,%5,%6,%7}, {%8,%9}, {%0,%1,%2,%3};"
        : "+f"(d[0]), "+f"(d[1]), "+f"(d[2]), "+f"(d[3])
        : "r"(a[0]), "r"(a[1]), "r"(a[2]), "r"(a[3]), "r"(b0), "r"(b1));
}
__device__ __forceinline__ u32 h2(float lo, float hi) {
    __half2 v = __floats2half2_rn(lo, hi);
    return *reinterpret_cast<u32*>(&v);
}

// A m16k16 fragment (rows rb.., cols kb0.., stride S halves)
#define LDA(Areg, bp, rb, kb0, S) \
    ldsm4(Areg, sadd((bp) + ((rb) + (lam & 15)) * (S) + (kb0) + (lam >> 4) * 8))
// B (k-major source): two n8-tiles (nb, nb+8) x k16 at kb0
#define LDB4(Breg, bp, nb, kb0, S) \
    ldsm4(Breg, sadd((bp) + ((nb) + ((lam >> 4) & 1) * 8 + (lam & 7)) * (S) + (kb0) + ((lam >> 3) & 1) * 8))

__device__ __forceinline__ void ln32(float (&v)[32], const float* g, const float* be) {
    float mu = 0.0f;
#pragma unroll
    for (int i = 0; i < 32; i++) mu += v[i];
    mu *= (1.0f / 32.0f);
    float var = 0.0f;
#pragma unroll
    for (int i = 0; i < 32; i++) { float d = v[i] - mu; var = fmaf(d, d, var); }
    var *= (1.0f / 32.0f);
    float rstd = rsqrtf(var + 1e-5f);
#pragma unroll
    for (int i = 0; i < 32; i++) v[i] = fmaf((v[i] - mu) * rstd, g[i], be[i]);
}

__global__ void __launch_bounds__(256, 3) block_fused(
    const float* __restrict__ x,
    const float* __restrict__ Wq, const float* __restrict__ Wk, const float* __restrict__ Wv,
    const float* __restrict__ Wo, const float* __restrict__ bo,
    const float* __restrict__ W1, const float* __restrict__ b1,
    const float* __restrict__ W2, const float* __restrict__ b2,
    const float* __restrict__ g1, const float* __restrict__ be1,
    const float* __restrict__ g2, const float* __restrict__ be2,
    float* __restrict__ out)
{
    extern __shared__ char smraw[];
    float* smf = reinterpret_cast<float*>(smraw);
    __half* smh = reinterpret_cast<__half*>(smraw + 4 * F_END);

    const int tid = threadIdx.x;
    const int t = tid;                       // token row for scalar phases (tid < 128)
    const int lam = tid & 31, w = tid >> 5;  // 8 warps
    const int lr = lam >> 2, lc = lam & 3;
    const size_t rowbase = ((size_t)blockIdx.x * TT + t) * DMM;

    // early x row load (rows 0..127 only)
    float4 xv4[8];
    if (t < TT) {
        const float4* xrow = reinterpret_cast<const float4*>(x + rowbase);
#pragma unroll
        for (int i = 0; i < 8; i++) xv4[i] = xrow[i];
    }

    // ---- stage WqkvT [96 n][40 k=d]; n: 0-31 Q, 32-63 K, 64-95 V; within: h*16+kk ----
    for (int i = tid; i < 3072; i += 256) {
        int n = i >> 5, d = i & 31;
        int sel = n >> 5, j = n & 31, hj = j >> 4, kk = j & 15;
        const float* Wsrc = (sel == 0) ? Wq : (sel == 1) ? Wk : Wv;
        smh[H_WB + n * 40 + d] = __float2half_rn(Wsrc[hj * 512 + d * 16 + kk]);
    }
    if (tid < 32) {
        smf[F_BO  + tid] = bo[tid];  smf[F_B2  + tid] = b2[tid];
        smf[F_G1  + tid] = g1[tid];  smf[F_BE1 + tid] = be1[tid];
        smf[F_G2  + tid] = g2[tid];  smf[F_BE2 + tid] = be2[tid];
    }
    if (tid < 128) smf[F_B1 + tid] = b1[tid];
    __syncthreads();

    // ---- LN1 (scalar, rows 0..127); xn kept in regs; write half row to XN ----
    float xn[32];
    if (t < TT) {
#pragma unroll
        for (int i = 0; i < 8; i++) {
            xn[4*i+0] = xv4[i].x; xn[4*i+1] = xv4[i].y;
            xn[4*i+2] = xv4[i].z; xn[4*i+3] = xv4[i].w;
        }
        ln32(xn, smf + F_G1, smf + F_BE1);
        u32* xr = reinterpret_cast<u32*>(smh + H_XN + t * 40);
#pragma unroll
        for (int p = 0; p < 16; p++) xr[p] = h2(xn[2*p], xn[2*p+1]);
    }
    __syncthreads();

    // ================= QKV: [128,32] @ [32,96]; warp owns 16 rows =================
    {
        const int rb = w * 16;
        u32 A[2][4];
        LDA(A[0], smh + H_XN, rb, 0,  40);
        LDA(A[1], smh + H_XN, rb, 16, 40);
#pragma unroll
        for (int np = 0; np < 6; np++) {
            float c[2][4];
#pragma unroll
            for (int b = 0; b < 2; b++)
#pragma unroll
                for (int q = 0; q < 4; q++) c[b][q] = 0.f;
#pragma unroll
            for (int kt = 0; kt < 2; kt++) {
                u32 Bv[4];
                LDB4(Bv, smh + H_WB, np * 16, kt * 16, 40);
                mma16a(c[0], A[kt], Bv[0], Bv[1]);
                mma16a(c[1], A[kt], Bv[2], Bv[3]);
            }
#pragma unroll
            for (int ntl = 0; ntl < 2; ntl++) {
                const int nt = 2 * np + ntl;
                const int sel = nt >> 2, colb = (nt & 3) * 8 + 2 * lc;
                if (sel < 2) {
                    __half* dst = smh + (sel == 0 ? H_QS : H_KS);
                    *reinterpret_cast<u32*>(&dst[(rb + lr)     * 40 + colb]) = h2(c[ntl][0], c[ntl][1]);
                    *reinterpret_cast<u32*>(&dst[(rb + lr + 8) * 40 + colb]) = h2(c[ntl][2], c[ntl][3]);
                } else {  // V transposed: Vt[dv][token]
                    smh[H_VT + colb       * 136 + rb + lr]     = __float2half_rn(c[ntl][0]);
                    smh[H_VT + (colb + 1) * 136 + rb + lr]     = __float2half_rn(c[ntl][1]);
                    smh[H_VT + colb       * 136 + rb + lr + 8] = __float2half_rn(c[ntl][2]);
                    smh[H_VT + (colb + 1) * 136 + rb + lr + 8] = __float2half_rn(c[ntl][3]);
                }
            }
        }
    }
    __syncthreads();

    // ================= causal attention: warp = (head, balanced qt pair {ws, 7-ws}) =================
    // P repacked in registers (FA2 trick). kb loop split: full blocks (no mask) + diagonal (masked).
    {
        const int h = w & 1, ws = w >> 1;
#pragma unroll
        for (int qi = 0; qi < 2; qi++) {
            const int qt = qi ? (7 - ws) : ws;    // depths: 5/5/4/4 key-blocks per warp
            const int nkb = (qt >> 1) + 1;
            u32 QA[4];
            LDA(QA, smh + H_QS, qt * 16, h * 16, 40);
            float o[2][4];
#pragma unroll
            for (int b = 0; b < 2; b++)
#pragma unroll
                for (int q = 0; q < 4; q++) o[b][q] = 0.f;
            float l_lo = 0.f, l_hi = 0.f;
            const int q_lo = qt * 16 + lr, q_hi = q_lo + 8;
            // ---- full (unmasked) key-blocks: all keys < qt*16 <= q_lo ----
            for (int kb = 0; kb < nkb - 1; kb++) {
                float s[4][4];
#pragma unroll
                for (int n2 = 0; n2 < 2; n2++) {
                    u32 Bv[4];
                    LDB4(Bv, smh + H_KS, kb * 32 + n2 * 16, h * 16, 40);
                    s[2*n2][0] = s[2*n2][1] = s[2*n2][2] = s[2*n2][3] = 0.f;
                    s[2*n2+1][0] = s[2*n2+1][1] = s[2*n2+1][2] = s[2*n2+1][3] = 0.f;
                    mma16a(s[2*n2],     QA, Bv[0], Bv[1]);
                    mma16a(s[2*n2 + 1], QA, Bv[2], Bv[3]);
                }
                u32 PA[2][4];
#pragma unroll
                for (int ntk = 0; ntk < 4; ntk++) {
                    float p0 = __expf(s[ntk][0]);
                    float p1 = __expf(s[ntk][1]);
                    float p2 = __expf(s[ntk][2]);
                    float p3 = __expf(s[ntk][3]);
                    l_lo += p0 + p1;  l_hi += p2 + p3;
                    PA[ntk >> 1][(ntk & 1) * 2]     = h2(p0, p1);
                    PA[ntk >> 1][(ntk & 1) * 2 + 1] = h2(p2, p3);
                }
#pragma unroll
                for (int ks = 0; ks < 2; ks++) {
                    u32 Vv[4];
                    LDB4(Vv, smh + H_VT, h * 16, kb * 32 + ks * 16, 136);
                    mma16a(o[0], PA[ks], Vv[0], Vv[1]);
                    mma16a(o[1], PA[ks], Vv[2], Vv[3]);
                }
            }
            // ---- diagonal (masked) key-block ----
            {
                const int kb = nkb - 1;
                float s[4][4];
#pragma unroll
                for (int n2 = 0; n2 < 2; n2++) {
                    u32 Bv[4];
                    LDB4(Bv, smh + H_KS, kb * 32 + n2 * 16, h * 16, 40);
                    s[2*n2][0] = s[2*n2][1] = s[2*n2][2] = s[2*n2][3] = 0.f;
                    s[2*n2+1][0] = s[2*n2+1][1] = s[2*n2+1][2] = s[2*n2+1][3] = 0.f;
                    mma16a(s[2*n2],     QA, Bv[0], Bv[1]);
                    mma16a(s[2*n2 + 1], QA, Bv[2], Bv[3]);
                }
                u32 PA[2][4];
#pragma unroll
                for (int ntk = 0; ntk < 4; ntk++) {
                    const int key0 = kb * 32 + ntk * 8 + 2 * lc;
                    float p0 = (key0     <= q_lo) ? __expf(s[ntk][0]) : 0.f;
                    float p1 = (key0 + 1 <= q_lo) ? __expf(s[ntk][1]) : 0.f;
                    float p2 = (key0     <= q_hi) ? __expf(s[ntk][2]) : 0.f;
                    float p3 = (key0 + 1 <= q_hi) ? __expf(s[ntk][3]) : 0.f;
                    l_lo += p0 + p1;  l_hi += p2 + p3;
                    PA[ntk >> 1][(ntk & 1) * 2]     = h2(p0, p1);
                    PA[ntk >> 1][(ntk & 1) * 2 + 1] = h2(p2, p3);
                }
#pragma unroll
                for (int ks = 0; ks < 2; ks++) {
                    u32 Vv[4];
                    LDB4(Vv, smh + H_VT, h * 16, kb * 32 + ks * 16, 136);
                    mma16a(o[0], PA[ks], Vv[0], Vv[1]);
                    mma16a(o[1], PA[ks], Vv[2], Vv[3]);
                }
            }
            l_lo += __shfl_xor_sync(0xffffffffu, l_lo, 1);
            l_lo += __shfl_xor_sync(0xffffffffu, l_lo, 2);
            l_hi += __shfl_xor_sync(0xffffffffu, l_hi, 1);
            l_hi += __shfl_xor_sync(0xffffffffu, l_hi, 2);
            const float il = __fdividef(1.f, l_lo), ih = __fdividef(1.f, l_hi);
            const int qr = qt * 16;
#pragma unroll
            for (int nv = 0; nv < 2; nv++) {
                *reinterpret_cast<u32*>(&smh[H_XN + (qr + lr)     * 40 + h*16 + nv*8 + 2*lc]) =
                    h2(o[nv][0] * il, o[nv][1] * il);
                *reinterpret_cast<u32*>(&smh[H_XN + (qr + lr + 8) * 40 + h*16 + nv*8 + 2*lc]) =
                    h2(o[nv][2] * ih, o[nv][3] * ih);
            }
        }
    }
    __syncthreads();

    // ---- stage WoT [32 c][40 j], W1t [128 j][40 d], W2t [32 c][136 j] ----
    for (int i = tid; i < 1024; i += 256) {
        int j = i >> 5, c = i & 31;
        smh[H_WB + c * 40 + j] = __float2half_rn(Wo[i]);      // i = j*32 + c
    }
    for (int i = tid; i < 4096; i += 256) {
        int d = i >> 7, j1 = i & 127;
        smh[H_QS + j1 * 40 + d] = __float2half_rn(W1[i]);     // i = d*128 + j1
        int j2 = i >> 5, c = i & 31;
        smh[H_KS + c * 136 + j2] = __float2half_rn(W2[i]);    // i = j2*32 + c
    }
    __syncthreads();

    // ================= Wo: [128,32] @ [32,32] -> OS (f32); warp = 16 rows =================
    {
        const int rb = w * 16;
        u32 A[2][4];
        LDA(A[0], smh + H_XN, rb, 0,  40);
        LDA(A[1], smh + H_XN, rb, 16, 40);
        float c[4][4];
#pragma unroll
        for (int b = 0; b < 4; b++)
#pragma unroll
            for (int q = 0; q < 4; q++) c[b][q] = 0.f;
#pragma unroll
        for (int kt = 0; kt < 2; kt++) {
#pragma unroll
            for (int n2 = 0; n2 < 2; n2++) {
                u32 Bv[4];
                LDB4(Bv, smh + H_WB, n2 * 16, kt * 16, 40);
                mma16a(c[2*n2],     A[kt], Bv[0], Bv[1]);
                mma16a(c[2*n2 + 1], A[kt], Bv[2], Bv[3]);
            }
        }
#pragma unroll
        for (int nt = 0; nt < 4; nt++) {
            *reinterpret_cast<float2*>(&smf[F_OS + (rb + lr)     * 36 + nt*8 + 2*lc]) =
                make_float2(c[nt][0], c[nt][1]);
            *reinterpret_cast<float2*>(&smf[F_OS + (rb + lr + 8) * 36 + nt*8 + 2*lc]) =
                make_float2(c[nt][2], c[nt][3]);
        }
    }
    __syncthreads();

    // ---- residual + LN2 (scalar, rows 0..127); write ZN half into XN ----
    float z[32];
    if (t < TT) {
        const float* os = smf + F_OS + t * 36;
#pragma unroll
        for (int c = 0; c < 32; c++) z[c] = xn[c] + os[c] + smf[F_BO + c];
        ln32(z, smf + F_G2, smf + F_BE2);
        u32* zr = reinterpret_cast<u32*>(smh + H_XN + t * 40);
#pragma unroll
        for (int p = 0; p < 16; p++) zr[p] = h2(z[2*p], z[2*p+1]);
    }
    __syncthreads();

    // ================= FFN: relu(ZN@W1+b1)@W2, H repacked in registers =================
    {
        const int rb = w * 16;
        u32 A[2][4];
        LDA(A[0], smh + H_XN, rb, 0,  40);
        LDA(A[1], smh + H_XN, rb, 16, 40);
        float cf[4][4];
#pragma unroll
        for (int b = 0; b < 4; b++)
#pragma unroll
            for (int q = 0; q < 4; q++) cf[b][q] = 0.f;
#pragma unroll
        for (int g = 0; g < 8; g++) {
            float hv[2][4];
#pragma unroll
            for (int b = 0; b < 2; b++)
#pragma unroll
                for (int q = 0; q < 4; q++) hv[b][q] = 0.f;
#pragma unroll
            for (int kt = 0; kt < 2; kt++) {
                u32 Bv[4];
                LDB4(Bv, smh + H_QS, g * 16, kt * 16, 40);
                mma16a(hv[0], A[kt], Bv[0], Bv[1]);
                mma16a(hv[1], A[kt], Bv[2], Bv[3]);
            }
            u32 PA[4];
#pragma unroll
            for (int ntl = 0; ntl < 2; ntl++) {
                const int nt = 2 * g + ntl;
                const float bj0 = smf[F_B1 + nt*8 + 2*lc];
                const float bj1 = smf[F_B1 + nt*8 + 2*lc + 1];
                float p0 = fmaxf(hv[ntl][0] + bj0, 0.f);
                float p1 = fmaxf(hv[ntl][1] + bj1, 0.f);
                float p2 = fmaxf(hv[ntl][2] + bj0, 0.f);
                float p3 = fmaxf(hv[ntl][3] + bj1, 0.f);
                PA[ntl * 2]     = h2(p0, p1);
                PA[ntl * 2 + 1] = h2(p2, p3);
            }
#pragma unroll
            for (int n2 = 0; n2 < 2; n2++) {
                u32 Bv[4];
                LDB4(Bv, smh + H_KS, n2 * 16, g * 16, 136);
                mma16a(cf[2*n2],     PA, Bv[0], Bv[1]);
                mma16a(cf[2*n2 + 1], PA, Bv[2], Bv[3]);
            }
        }
#pragma unroll
        for (int nt2 = 0; nt2 < 4; nt2++) {
            *reinterpret_cast<float2*>(&smf[F_OS + (rb + lr)     * 36 + nt2*8 + 2*lc]) =
                make_float2(cf[nt2][0], cf[nt2][1]);
            *reinterpret_cast<float2*>(&smf[F_OS + (rb + lr + 8) * 36 + nt2*8 + 2*lc]) =
                make_float2(cf[nt2][2], cf[nt2][3]);
        }
    }
    __syncthreads();

    // ---- final residual + store (rows 0..127) ----
    if (t < TT) {
        const float* r = smf + F_OS + t * 36;
        float4* o4 = reinterpret_cast<float4*>(out + rowbase);
#pragma unroll
        for (int c4 = 0; c4 < 8; c4++)
            o4[c4] = make_float4(z[4*c4+0] + r[4*c4+0] + smf[F_B2 + 4*c4+0],
                                 z[4*c4+1] + r[4*c4+1] + smf[F_B2 + 4*c4+1],
                                 z[4*c4+2] + r[4*c4+2] + smf[F_B2 + 4*c4+2],
                                 z[4*c4+3] + r[4*c4+3] + smf[F_B2 + 4*c4+3]);
    }
}

extern "C" void kernel_launch(void* const* d_in, const int* in_sizes, int n_in,
                              void* d_out, int out_size) {
    const float* x   = (const float*)d_in[0];
    const float* Wq  = (const float*)d_in[1];
    const float* Wk  = (const float*)d_in[2];
    const float* Wv  = (const float*)d_in[3];
    const float* Wo  = (const float*)d_in[4];
    const float* bo  = (const float*)d_in[5];
    const float* W1  = (const float*)d_in[6];
    const float* b1  = (const float*)d_in[7];
    const float* W2  = (const float*)d_in[8];
    const float* b2  = (const float*)d_in[9];
    const float* g1  = (const float*)d_in[10];
    const float* be1 = (const float*)d_in[11];
    const float* g2  = (const float*)d_in[12];
    const float* be2 = (const float*)d_in[13];

    int B = in_sizes[0] / (TT * DMM);
    cudaFuncSetAttribute(block_fused, cudaFuncAttributeMaxDynamicSharedMemorySize, SMEM_BYTES);
    block_fused<<<B, 256, SMEM_BYTES>>>(x, Wq, Wk, Wv, Wo, bo, W1, b1, W2, b2,
                                        g1, be1, g2, be2, (float*)d_out);
}

// round 17
// speedup vs baseline: 1.0477x; 1.0477x over previous
#include <cuda_runtime.h>
#include <cuda_fp16.h>
#include <math.h>
#include <stdint.h>

#define TT 128
#define DMM 32

typedef uint32_t u32;

// ---- f32 region (float offsets) ----
#define F_BO   0
#define F_B2   32
#define F_G1   64
#define F_BE1  96
#define F_G2   128
#define F_BE2  160
#define F_B1   192          // 128 floats
#define F_OS   320          // [128][36] f32 (Wo out, then FFN out)
#define F_END  (320 + 128*36)
// ---- half region (half offsets), starts at byte 4*F_END ----
#define H_XN   0            // [128][40]  xn -> at -> zn
#define H_QS   5120         // [128][40]  Q  -> W1t[128][40]
#define H_KS   10240        // [128][40]  K  -> W2t[32][136]
#define H_VT   15360        // [32][136]  V^T (dv-major, keys contiguous)
#define H_WB   19712        // [96][40] WqkvT -> WoT[32][40]
#define H_END  23552
#define SMEM_BYTES (4*F_END + 2*H_END)   // 66816

__device__ __forceinline__ u32 sadd(const __half* p) {
    return static_cast<u32>(__cvta_generic_to_shared(p));
}
__device__ __forceinline__ void ldsm4(u32 (&r)[4], u32 a) {
    asm volatile("ldmatrix.sync.aligned.m8n8.x4.shared.b16 {%0,%1,%2,%3}, [%4];"
                 : "=r"(r[0]), "=r"(r[1]), "=r"(r[2]), "=r"(r[3]) : "r"(a));
}
// D += A(16x16,row) * B(16x8,col), f16 in, f32 accum
__device__ __forceinline__ void mma16a(float (&d)[4], const u32 (&a)[4], u32 b0, u32 b1) {
    asm("mma.sync.aligned.m16n8k16.row.col.f32.f16.f16.f32 "
        "{%0,%1,%2,%3}, {%4,%5,%6,%7}, {%8,%9}, {%0,%1,%2,%3};"
        : "+f"(d[0]), "+f"(d[1]), "+f"(d[2]), "+f"(d[3])
        : "r"(a[0]), "r"(a[1]), "r"(a[2]), "r"(a[3]), "r"(b0), "r"(b1));
}
__device__ __forceinline__ u32 h2(float lo, float hi) {
    __half2 v = __floats2half2_rn(lo, hi);
    return *reinterpret_cast<u32*>(&v);
}

// A m16k16 fragment (rows rb.., cols kb0.., stride S halves)
#define LDA(Areg, bp, rb, kb0, S) \
    ldsm4(Areg, sadd((bp) + ((rb) + (lam & 15)) * (S) + (kb0) + (lam >> 4) * 8))
// B (k-major source): two n8-tiles (nb, nb+8) x k16 at kb0
#define LDB4(Breg, bp, nb, kb0, S) \
    ldsm4(Breg, sadd((bp) + ((nb) + ((lam >> 4) & 1) * 8 + (lam & 7)) * (S) + (kb0) + ((lam >> 3) & 1) * 8))

__device__ __forceinline__ void ln32(float (&v)[32], const float* g, const float* be) {
    float mu = 0.0f;
#pragma unroll
    for (int i = 0; i < 32; i++) mu += v[i];
    mu *= (1.0f / 32.0f);
    float var = 0.0f;
#pragma unroll
    for (int i = 0; i < 32; i++) { float d = v[i] - mu; var = fmaf(d, d, var); }
    var *= (1.0f / 32.0f);
    float rstd = rsqrtf(var + 1e-5f);
#pragma unroll
    for (int i = 0; i < 32; i++) v[i] = fmaf((v[i] - mu) * rstd, g[i], be[i]);
}

__global__ void __launch_bounds__(256, 3) block_fused(
    const float* __restrict__ x,
    const float* __restrict__ Wq, const float* __restrict__ Wk, const float* __restrict__ Wv,
    const float* __restrict__ Wo, const float* __restrict__ bo,
    const float* __restrict__ W1, const float* __restrict__ b1,
    const float* __restrict__ W2, const float* __restrict__ b2,
    const float* __restrict__ g1, const float* __restrict__ be1,
    const float* __restrict__ g2, const float* __restrict__ be2,
    float* __restrict__ out)
{
    extern __shared__ char smraw[];
    float* smf = reinterpret_cast<float*>(smraw);
    __half* smh = reinterpret_cast<__half*>(smraw + 4 * F_END);

    const int tid = threadIdx.x;
    const int t = tid;                       // token row for scalar phases (tid < 128)
    const int lam = tid & 31, w = tid >> 5;  // 8 warps
    const int lr = lam >> 2, lc = lam & 3;
    const size_t rowbase = ((size_t)blockIdx.x * TT + t) * DMM;

    // early x row load (rows 0..127 only)
    float4 xv4[8];
    if (t < TT) {
        const float4* xrow = reinterpret_cast<const float4*>(x + rowbase);
#pragma unroll
        for (int i = 0; i < 8; i++) xv4[i] = xrow[i];
    }

    // ---- stage WqkvT [96 n][40 k=d]; SOURCE-LINEAR (coalesced LDG) ----
    // r = hj*512 + d*16 + kk  ->  src = Wsrc[r]; n = sel*32 + hj*16 + kk; dst = n*40+d.
    // Same (src,dst) mapping as before, just iterated in source order.
    for (int i = tid; i < 3072; i += 256) {
        int sel = i >> 10, r = i & 1023;
        int kk = r & 15, d = (r >> 4) & 31, hj = r >> 9;
        const float* Wsrc = (sel == 0) ? Wq : (sel == 1) ? Wk : Wv;
        int n = sel * 32 + hj * 16 + kk;
        smh[H_WB + n * 40 + d] = __float2half_rn(Wsrc[r]);
    }
    if (tid < 32) {
        smf[F_BO  + tid] = bo[tid];  smf[F_B2  + tid] = b2[tid];
        smf[F_G1  + tid] = g1[tid];  smf[F_BE1 + tid] = be1[tid];
        smf[F_G2  + tid] = g2[tid];  smf[F_BE2 + tid] = be2[tid];
    }
    if (tid < 128) smf[F_B1 + tid] = b1[tid];
    __syncthreads();

    // ---- LN1 (scalar, rows 0..127); xn kept in regs; write half row to XN ----
    float xn[32];
    if (t < TT) {
#pragma unroll
        for (int i = 0; i < 8; i++) {
            xn[4*i+0] = xv4[i].x; xn[4*i+1] = xv4[i].y;
            xn[4*i+2] = xv4[i].z; xn[4*i+3] = xv4[i].w;
        }
        ln32(xn, smf + F_G1, smf + F_BE1);
        u32* xr = reinterpret_cast<u32*>(smh + H_XN + t * 40);
#pragma unroll
        for (int p = 0; p < 16; p++) xr[p] = h2(xn[2*p], xn[2*p+1]);
    }
    __syncthreads();

    // ================= QKV: [128,32] @ [32,96]; warp owns 16 rows =================
    {
        const int rb = w * 16;
        u32 A[2][4];
        LDA(A[0], smh + H_XN, rb, 0,  40);
        LDA(A[1], smh + H_XN, rb, 16, 40);
#pragma unroll
        for (int np = 0; np < 6; np++) {
            float c[2][4];
#pragma unroll
            for (int b = 0; b < 2; b++)
#pragma unroll
                for (int q = 0; q < 4; q++) c[b][q] = 0.f;
#pragma unroll
            for (int kt = 0; kt < 2; kt++) {
                u32 Bv[4];
                LDB4(Bv, smh + H_WB, np * 16, kt * 16, 40);
                mma16a(c[0], A[kt], Bv[0], Bv[1]);
                mma16a(c[1], A[kt], Bv[2], Bv[3]);
            }
#pragma unroll
            for (int ntl = 0; ntl < 2; ntl++) {
                const int nt = 2 * np + ntl;
                const int sel = nt >> 2, colb = (nt & 3) * 8 + 2 * lc;
                if (sel < 2) {
                    __half* dst = smh + (sel == 0 ? H_QS : H_KS);
                    *reinterpret_cast<u32*>(&dst[(rb + lr)     * 40 + colb]) = h2(c[ntl][0], c[ntl][1]);
                    *reinterpret_cast<u32*>(&dst[(rb + lr + 8) * 40 + colb]) = h2(c[ntl][2], c[ntl][3]);
                } else {  // V transposed: Vt[dv][token]
                    smh[H_VT + colb       * 136 + rb + lr]     = __float2half_rn(c[ntl][0]);
                    smh[H_VT + (colb + 1) * 136 + rb + lr]     = __float2half_rn(c[ntl][1]);
                    smh[H_VT + colb       * 136 + rb + lr + 8] = __float2half_rn(c[ntl][2]);
                    smh[H_VT + (colb + 1) * 136 + rb + lr + 8] = __float2half_rn(c[ntl][3]);
                }
            }
        }
    }
    __syncthreads();

    // ================= causal attention: warp = (head, balanced qt pair {ws, 7-ws}) =================
    // P repacked in registers (FA2 trick). kb loop split: full blocks (no mask) + diagonal (masked).
    {
        const int h = w & 1, ws = w >> 1;
#pragma unroll
        for (int qi = 0; qi < 2; qi++) {
            const int qt = qi ? (7 - ws) : ws;    // depths: 5/5/4/4 key-blocks per warp
            const int nkb = (qt >> 1) + 1;
            u32 QA[4];
            LDA(QA, smh + H_QS, qt * 16, h * 16, 40);
            float o[2][4];
#pragma unroll
            for (int b = 0; b < 2; b++)
#pragma unroll
                for (int q = 0; q < 4; q++) o[b][q] = 0.f;
            float l_lo = 0.f, l_hi = 0.f;
            const int q_lo = qt * 16 + lr, q_hi = q_lo + 8;
            // ---- full (unmasked) key-blocks: all keys < qt*16 <= q_lo ----
            for (int kb = 0; kb < nkb - 1; kb++) {
                float s[4][4];
#pragma unroll
                for (int n2 = 0; n2 < 2; n2++) {
                    u32 Bv[4];
                    LDB4(Bv, smh + H_KS, kb * 32 + n2 * 16, h * 16, 40);
                    s[2*n2][0] = s[2*n2][1] = s[2*n2][2] = s[2*n2][3] = 0.f;
                    s[2*n2+1][0] = s[2*n2+1][1] = s[2*n2+1][2] = s[2*n2+1][3] = 0.f;
                    mma16a(s[2*n2],     QA, Bv[0], Bv[1]);
                    mma16a(s[2*n2 + 1], QA, Bv[2], Bv[3]);
                }
                u32 PA[2][4];
#pragma unroll
                for (int ntk = 0; ntk < 4; ntk++) {
                    float p0 = __expf(s[ntk][0]);
                    float p1 = __expf(s[ntk][1]);
                    float p2 = __expf(s[ntk][2]);
                    float p3 = __expf(s[ntk][3]);
                    l_lo += p0 + p1;  l_hi += p2 + p3;
                    PA[ntk >> 1][(ntk & 1) * 2]     = h2(p0, p1);
                    PA[ntk >> 1][(ntk & 1) * 2 + 1] = h2(p2, p3);
                }
#pragma unroll
                for (int ks = 0; ks < 2; ks++) {
                    u32 Vv[4];
                    LDB4(Vv, smh + H_VT, h * 16, kb * 32 + ks * 16, 136);
                    mma16a(o[0], PA[ks], Vv[0], Vv[1]);
                    mma16a(o[1], PA[ks], Vv[2], Vv[3]);
                }
            }
            // ---- diagonal (masked) key-block ----
            {
                const int kb = nkb - 1;
                float s[4][4];
#pragma unroll
                for (int n2 = 0; n2 < 2; n2++) {
                    u32 Bv[4];
                    LDB4(Bv, smh + H_KS, kb * 32 + n2 * 16, h * 16, 40);
                    s[2*n2][0] = s[2*n2][1] = s[2*n2][2] = s[2*n2][3] = 0.f;
                    s[2*n2+1][0] = s[2*n2+1][1] = s[2*n2+1][2] = s[2*n2+1][3] = 0.f;
                    mma16a(s[2*n2],     QA, Bv[0], Bv[1]);
                    mma16a(s[2*n2 + 1], QA, Bv[2], Bv[3]);
                }
                u32 PA[2][4];
#pragma unroll
                for (int ntk = 0; ntk < 4; ntk++) {
                    const int key0 = kb * 32 + ntk * 8 + 2 * lc;
                    float p0 = (key0     <= q_lo) ? __expf(s[ntk][0]) : 0.f;
                    float p1 = (key0 + 1 <= q_lo) ? __expf(s[ntk][1]) : 0.f;
                    float p2 = (key0     <= q_hi) ? __expf(s[ntk][2]) : 0.f;
                    float p3 = (key0 + 1 <= q_hi) ? __expf(s[ntk][3]) : 0.f;
                    l_lo += p0 + p1;  l_hi += p2 + p3;
                    PA[ntk >> 1][(ntk & 1) * 2]     = h2(p0, p1);
                    PA[ntk >> 1][(ntk & 1) * 2 + 1] = h2(p2, p3);
                }
#pragma unroll
                for (int ks = 0; ks < 2; ks++) {
                    u32 Vv[4];
                    LDB4(Vv, smh + H_VT, h * 16, kb * 32 + ks * 16, 136);
                    mma16a(o[0], PA[ks], Vv[0], Vv[1]);
                    mma16a(o[1], PA[ks], Vv[2], Vv[3]);
                }
            }
            l_lo += __shfl_xor_sync(0xffffffffu, l_lo, 1);
            l_lo += __shfl_xor_sync(0xffffffffu, l_lo, 2);
            l_hi += __shfl_xor_sync(0xffffffffu, l_hi, 1);
            l_hi += __shfl_xor_sync(0xffffffffu, l_hi, 2);
            const float il = __fdividef(1.f, l_lo), ih = __fdividef(1.f, l_hi);
            const int qr = qt * 16;
#pragma unroll
            for (int nv = 0; nv < 2; nv++) {
                *reinterpret_cast<u32*>(&smh[H_XN + (qr + lr)     * 40 + h*16 + nv*8 + 2*lc]) =
                    h2(o[nv][0] * il, o[nv][1] * il);
                *reinterpret_cast<u32*>(&smh[H_XN + (qr + lr + 8) * 40 + h*16 + nv*8 + 2*lc]) =
                    h2(o[nv][2] * ih, o[nv][3] * ih);
            }
        }
    }
    __syncthreads();

    // ---- stage WoT [32 c][40 j], W1t [128 j][40 d], W2t [32 c][136 j] (all source-linear LDG) ----
    for (int i = tid; i < 1024; i += 256) {
        int j = i >> 5, c = i & 31;
        smh[H_WB + c * 40 + j] = __float2half_rn(Wo[i]);      // i = j*32 + c
    }
    for (int i = tid; i < 4096; i += 256) {
        int d = i >> 7, j1 = i & 127;
        smh[H_QS + j1 * 40 + d] = __float2half_rn(W1[i]);     // i = d*128 + j1
        int j2 = i >> 5, c = i & 31;
        smh[H_KS + c * 136 + j2] = __float2half_rn(W2[i]);    // i = j2*32 + c
    }
    __syncthreads();

    // ================= Wo: [128,32] @ [32,32] -> OS (f32); warp = 16 rows =================
    {
        const int rb = w * 16;
        u32 A[2][4];
        LDA(A[0], smh + H_XN, rb, 0,  40);
        LDA(A[1], smh + H_XN, rb, 16, 40);
        float c[4][4];
#pragma unroll
        for (int b = 0; b < 4; b++)
#pragma unroll
            for (int q = 0; q < 4; q++) c[b][q] = 0.f;
#pragma unroll
        for (int kt = 0; kt < 2; kt++) {
#pragma unroll
            for (int n2 = 0; n2 < 2; n2++) {
                u32 Bv[4];
                LDB4(Bv, smh + H_WB, n2 * 16, kt * 16, 40);
                mma16a(c[2*n2],     A[kt], Bv[0], Bv[1]);
                mma16a(c[2*n2 + 1], A[kt], Bv[2], Bv[3]);
            }
        }
#pragma unroll
        for (int nt = 0; nt < 4; nt++) {
            *reinterpret_cast<float2*>(&smf[F_OS + (rb + lr)     * 36 + nt*8 + 2*lc]) =
                make_float2(c[nt][0], c[nt][1]);
            *reinterpret_cast<float2*>(&smf[F_OS + (rb + lr + 8) * 36 + nt*8 + 2*lc]) =
                make_float2(c[nt][2], c[nt][3]);
        }
    }
    __syncthreads();

    // ---- residual + LN2 (scalar, rows 0..127); write ZN half into XN ----
    float z[32];
    if (t < TT) {
        const float* os = smf + F_OS + t * 36;
#pragma unroll
        for (int c = 0; c < 32; c++) z[c] = xn[c] + os[c] + smf[F_BO + c];
        ln32(z, smf + F_G2, smf + F_BE2);
        u32* zr = reinterpret_cast<u32*>(smh + H_XN + t * 40);
#pragma unroll
        for (int p = 0; p < 16; p++) zr[p] = h2(z[2*p], z[2*p+1]);
    }
    __syncthreads();

    // ================= FFN: relu(ZN@W1+b1)@W2, H repacked in registers =================
    {
        const int rb = w * 16;
        u32 A[2][4];
        LDA(A[0], smh + H_XN, rb, 0,  40);
        LDA(A[1], smh + H_XN, rb, 16, 40);
        float cf[4][4];
#pragma unroll
        for (int b = 0; b < 4; b++)
#pragma unroll
            for (int q = 0; q < 4; q++) cf[b][q] = 0.f;
#pragma unroll
        for (int g = 0; g < 8; g++) {
            float hv[2][4];
#pragma unroll
            for (int b = 0; b < 2; b++)
#pragma unroll
                for (int q = 0; q < 4; q++) hv[b][q] = 0.f;
#pragma unroll
            for (int kt = 0; kt < 2; kt++) {
                u32 Bv[4];
                LDB4(Bv, smh + H_QS, g * 16, kt * 16, 40);
                mma16a(hv[0], A[kt], Bv[0], Bv[1]);
                mma16a(hv[1], A[kt], Bv[2], Bv[3]);
            }
            u32 PA[4];
#pragma unroll
            for (int ntl = 0; ntl < 2; ntl++) {
                const int nt = 2 * g + ntl;
                const float bj0 = smf[F_B1 + nt*8 + 2*lc];
                const float bj1 = smf[F_B1 + nt*8 + 2*lc + 1];
                float p0 = fmaxf(hv[ntl][0] + bj0, 0.f);
                float p1 = fmaxf(hv[ntl][1] + bj1, 0.f);
                float p2 = fmaxf(hv[ntl][2] + bj0, 0.f);
                float p3 = fmaxf(hv[ntl][3] + bj1, 0.f);
                PA[ntl * 2]     = h2(p0, p1);
                PA[ntl * 2 + 1] = h2(p2, p3);
            }
#pragma unroll
            for (int n2 = 0; n2 < 2; n2++) {
                u32 Bv[4];
                LDB4(Bv, smh + H_KS, n2 * 16, g * 16, 136);
                mma16a(cf[2*n2],     PA, Bv[0], Bv[1]);
                mma16a(cf[2*n2 + 1], PA, Bv[2], Bv[3]);
            }
        }
#pragma unroll
        for (int nt2 = 0; nt2 < 4; nt2++) {
            *reinterpret_cast<float2*>(&smf[F_OS + (rb + lr)     * 36 + nt2*8 + 2*lc]) =
                make_float2(cf[nt2][0], cf[nt2][1]);
            *reinterpret_cast<float2*>(&smf[F_OS + (rb + lr + 8) * 36 + nt2*8 + 2*lc]) =
                make_float2(cf[nt2][2], cf[nt2][3]);
        }
    }
    __syncthreads();

    // ---- final residual + store (rows 0..127) ----
    if (t < TT) {
        const float* r = smf + F_OS + t * 36;
        float4* o4 = reinterpret_cast<float4*>(out + rowbase);
#pragma unroll
        for (int c4 = 0; c4 < 8; c4++)
            o4[c4] = make_float4(z[4*c4+0] + r[4*c4+0] + smf[F_B2 + 4*c4+0],
                                 z[4*c4+1] + r[4*c4+1] + smf[F_B2 + 4*c4+1],
                                 z[4*c4+2] + r[4*c4+2] + smf[F_B2 + 4*c4+2],
                                 z[4*c4+3] + r[4*c4+3] + smf[F_B2 + 4*c4+3]);
    }
}

extern "C" void kernel_launch(void* const* d_in, const int* in_sizes, int n_in,
                              void* d_out, int out_size) {
    const float* x   = (const float*)d_in[0];
    const float* Wq  = (const float*)d_in[1];
    const float* Wk  = (const float*)d_in[2];
    const float* Wv  = (const float*)d_in[3];
    const float* Wo  = (const float*)d_in[4];
    const float* bo  = (const float*)d_in[5];
    const float* W1  = (const float*)d_in[6];
    const float* b1  = (const float*)d_in[7];
    const float* W2  = (const float*)d_in[8];
    const float* b2  = (const float*)d_in[9];
    const float* g1  = (const float*)d_in[10];
    const float* be1 = (const float*)d_in[11];
    const float* g2  = (const float*)d_in[12];
    const float* be2 = (const float*)d_in[13];

    int B = in_sizes[0] / (TT * DMM);
    cudaFuncSetAttribute(block_fused, cudaFuncAttributeMaxDynamicSharedMemorySize, SMEM_BYTES);
    block_fused<<<B, 256, SMEM_BYTES>>>(x, Wq, Wk, Wv, Wo, bo, W1, b1, W2, b2,
                                        g1, be1, g2, be2, (float*)d_out);
}